// round 13
// baseline (speedup 1.0000x reference)
#include <cuda_runtime.h>

// SphericalHarmonicsAttentionBias — tiled 3-phase fused kernel (sm_103a, fp32
// + packed fma.rn.f32x2).
//
// R10: the R8/R9 binder was L1 data-RETURN bandwidth (broadcast weights are
// replicated to every lane: ~8B/lane per ffma2). Fix: amortize weight bytes
// over 4 pairs per thread via a register-tiled layer-2 GEMM with activations
// staged in SMEM. Weight return drops 16B/ffma2 -> 2.5B/ffma2.
//
// CTA = 128 threads = tile of 128 pairs (fixed b,i ; j-tile of 128).
//   phase0: thread t -> pair t: SH + layer1 + SiLU -> At[64ch][128pair]
//   phase2: thread (g=t&31, c=t>>5): pairs 4g..4g+3 x channels 16c..16c+15
//           64-step k loop, 32 ffma2/step; SiLU; STS.128 back into At
//   phase3: pairs 4g..4g+3 x heads {2c,2c+1}; coalesced float4 stores.

#define S_DIM 1024
#define EPSF 1e-6f

static __device__ __forceinline__ unsigned long long pack2(float lo, float hi) {
    unsigned long long r;
    asm("mov.b64 %0, {%1, %2};" : "=l"(r) : "f"(lo), "f"(hi));
    return r;
}
static __device__ __forceinline__ void unpack2(unsigned long long v, float& lo, float& hi) {
    asm("mov.b64 {%0, %1}, %2;" : "=f"(lo), "=f"(hi) : "l"(v));
}
static __device__ __forceinline__ void ffma2(unsigned long long& d,
                                             unsigned long long a,
                                             unsigned long long b) {
    asm("fma.rn.f32x2 %0, %1, %2, %0;" : "+l"(d) : "l"(a), "l"(b));
}
static __device__ __forceinline__ float silu_f(float x) {
    return __fdividef(x, 1.0f + __expf(-x));
}

__global__ void __launch_bounds__(128, 3)
shab_kernel(const float* __restrict__ coords,
            const float* __restrict__ w1, const float* __restrict__ b1,
            const float* __restrict__ w2, const float* __restrict__ b2,
            const float* __restrict__ w3, const float* __restrict__ b3,
            float* __restrict__ out)
{
    __shared__ float At[64][128];                 // 32 KB, reused L1-out then L2-out
    __shared__ ulonglong2 w1q[9 * 16];            // 2.3 KB (quads of 4 fp32)
    __shared__ ulonglong2 w2q[64 * 16];           // 16 KB
    __shared__ unsigned long long w3d[64 * 4];    // 2 KB   (pairs of fp32)
    __shared__ ulonglong2 b1q[16];
    __shared__ ulonglong2 b2q[16];
    __shared__ unsigned long long b3d[4];

    const int tid = threadIdx.x;

    // ---- stage weights ----
    {
        const ulonglong2* g1 = (const ulonglong2*)w1;
        for (int x = tid; x < 9 * 16; x += 128) w1q[x] = g1[x];
        const ulonglong2* g2 = (const ulonglong2*)w2;
        for (int x = tid; x < 64 * 16; x += 128) w2q[x] = g2[x];
        const unsigned long long* g3 = (const unsigned long long*)w3;
        for (int x = tid; x < 64 * 4; x += 128) w3d[x] = g3[x];
        if (tid < 16)       b1q[tid]      = ((const ulonglong2*)b1)[tid];
        else if (tid < 32)  b2q[tid - 16] = ((const ulonglong2*)b2)[tid - 16];
        else if (tid < 36)  b3d[tid - 32] = ((const unsigned long long*)b3)[tid - 32];
    }

    const int i  = blockIdx.y;
    const int bb = blockIdx.z;
    const int j  = blockIdx.x * 128 + tid;
    const float* cb = coords + (size_t)bb * (S_DIM * 3);

    // ---- SH (independent of smem; overlaps weight staging) ----
    const float rx = cb[i * 3 + 0] - cb[j * 3 + 0];
    const float ry = cb[i * 3 + 1] - cb[j * 3 + 1];
    const float rz = cb[i * 3 + 2] - cb[j * 3 + 2];
    const float nrm = sqrtf(rx * rx + ry * ry + rz * rz);
    const float inv = __fdividef(1.0f, nrm + EPSF);
    float ux = rx * inv, uy = ry * inv, uz = rz * inv;
    const float un = sqrtf(ux * ux + uy * uy + uz * uz);
    const float sc = __fdividef(1.0f, fmaxf(un, EPSF));
    ux *= sc; uy *= sc; uz *= sc;

    const float C0    = 0.28209479177387814f;
    const float C1    = 0.48860251190291992f;
    const float C2    = 0.63078313050504009f;
    const float C2S3  = 1.09254843059207907f;
    const float C2S3H = 0.54627421529603953f;

    float sh[9];
    sh[0] = C0;
    sh[1] = C1 * ux;  sh[2] = C1 * uy;  sh[3] = C1 * uz;
    sh[4] = C2S3 * ux * uz;
    sh[5] = C2S3 * ux * uy;
    sh[6] = C2 * (uy * uy - 0.5f * (ux * ux + uz * uz));
    sh[7] = C2S3 * uy * uz;
    sh[8] = C2S3H * (uz * uz - ux * ux);

    __syncthreads();

    // ---- phase 0: layer 1 ([9]@[9,64]) + SiLU -> At[ch][pair] ----
    {
        unsigned long long acc[32];
#pragma unroll
        for (int q = 0; q < 16; q++) {
            const ulonglong2 bbv = b1q[q];
            acc[2 * q] = bbv.x;  acc[2 * q + 1] = bbv.y;
        }
#pragma unroll
        for (int k = 0; k < 9; k++) {
            const unsigned long long a = pack2(sh[k], sh[k]);
#pragma unroll
            for (int q = 0; q < 16; q++) {
                const ulonglong2 w = w1q[k * 16 + q];
                ffma2(acc[2 * q],     a, w.x);
                ffma2(acc[2 * q + 1], a, w.y);
            }
        }
#pragma unroll
        for (int n = 0; n < 32; n++) {
            float lo, hi; unpack2(acc[n], lo, hi);
            At[2 * n][tid]     = silu_f(lo);
            At[2 * n + 1][tid] = silu_f(hi);
        }
    }
    __syncthreads();

    const int g  = tid & 31;   // pair group: pairs 4g..4g+3
    const int c  = tid >> 5;   // chunk 0..3
    const int p0 = g * 4;

    // ---- phase 2: layer 2 GEMM, 4 pairs x 16 channels per thread ----
    unsigned long long acc2[4][8];   // acc2[p][m] = channels (16c+2m, 16c+2m+1)
    {
        const int n0q = c * 4;       // quad index of first channel
#pragma unroll
        for (int q = 0; q < 4; q++) {
            const ulonglong2 bv = b2q[n0q + q];
#pragma unroll
            for (int p = 0; p < 4; p++) {
                acc2[p][2 * q] = bv.x;  acc2[p][2 * q + 1] = bv.y;
            }
        }
#pragma unroll 4
        for (int k = 0; k < 64; k++) {
            const float4 a4 = *(const float4*)&At[k][p0];
            const unsigned long long a0 = pack2(a4.x, a4.x);
            const unsigned long long a1 = pack2(a4.y, a4.y);
            const unsigned long long a2 = pack2(a4.z, a4.z);
            const unsigned long long a3 = pack2(a4.w, a4.w);
#pragma unroll
            for (int q = 0; q < 4; q++) {
                const ulonglong2 w = w2q[k * 16 + n0q + q];
                ffma2(acc2[0][2 * q],     a0, w.x);  ffma2(acc2[0][2 * q + 1], a0, w.y);
                ffma2(acc2[1][2 * q],     a1, w.x);  ffma2(acc2[1][2 * q + 1], a1, w.y);
                ffma2(acc2[2][2 * q],     a2, w.x);  ffma2(acc2[2][2 * q + 1], a2, w.y);
                ffma2(acc2[3][2 * q],     a3, w.x);  ffma2(acc2[3][2 * q + 1], a3, w.y);
            }
        }
    }
    __syncthreads();   // all At reads done before overwrite

    // ---- SiLU + write layer-2 activations back into At ----
    {
#pragma unroll
        for (int m = 0; m < 8; m++) {
            float4 lo4, hi4;
            float l, h;
            unpack2(acc2[0][m], l, h); lo4.x = silu_f(l); hi4.x = silu_f(h);
            unpack2(acc2[1][m], l, h); lo4.y = silu_f(l); hi4.y = silu_f(h);
            unpack2(acc2[2][m], l, h); lo4.z = silu_f(l); hi4.z = silu_f(h);
            unpack2(acc2[3][m], l, h); lo4.w = silu_f(l); hi4.w = silu_f(h);
            const int n = c * 16 + 2 * m;
            *(float4*)&At[n][p0]     = lo4;
            *(float4*)&At[n + 1][p0] = hi4;
        }
    }
    __syncthreads();

    // ---- phase 3: layer 3 ([64]@[64,8]); 4 pairs x heads {2c, 2c+1} ----
    {
        unsigned long long acc3[4];
        const unsigned long long b3v = b3d[c];
#pragma unroll
        for (int p = 0; p < 4; p++) acc3[p] = b3v;
#pragma unroll 8
        for (int k = 0; k < 64; k++) {
            const float4 a4 = *(const float4*)&At[k][p0];
            const unsigned long long w = w3d[k * 4 + c];
            ffma2(acc3[0], pack2(a4.x, a4.x), w);
            ffma2(acc3[1], pack2(a4.y, a4.y), w);
            ffma2(acc3[2], pack2(a4.z, a4.z), w);
            ffma2(acc3[3], pack2(a4.w, a4.w), w);
        }
        float4 lo4, hi4;
        unpack2(acc3[0], lo4.x, hi4.x);
        unpack2(acc3[1], lo4.y, hi4.y);
        unpack2(acc3[2], lo4.z, hi4.z);
        unpack2(acc3[3], lo4.w, hi4.w);
        // out[((bb*8 + h)*S + i)*S + j], h = 2c (lo) and 2c+1 (hi)
        const size_t jbase = (size_t)blockIdx.x * 128 + p0;
        const size_t base  = (((size_t)bb * 8 + 2 * c) * S_DIM + i) * S_DIM + jbase;
        *(float4*)(out + base)                          = lo4;
        *(float4*)(out + base + (size_t)S_DIM * S_DIM)  = hi4;
    }
}

extern "C" void kernel_launch(void* const* d_in, const int* in_sizes, int n_in,
                              void* d_out, int out_size) {
    const float* coords = (const float*)d_in[0];
    const float* w1     = (const float*)d_in[1];
    const float* b1     = (const float*)d_in[2];
    const float* w2     = (const float*)d_in[3];
    const float* b2     = (const float*)d_in[4];
    const float* w3     = (const float*)d_in[5];
    const float* b3     = (const float*)d_in[6];
    float* out = (float*)d_out;

    dim3 grid(S_DIM / 128, S_DIM, 2);  // (j-tiles, i, b)
    shab_kernel<<<grid, 128>>>(coords, w1, b1, w2, b2, w3, b3, out);
}

// round 17
// speedup vs baseline: 1.3967x; 1.3967x over previous
#include <cuda_runtime.h>
#include <cstdint>

// SphericalHarmonicsAttentionBias — warp-level mma.sync (tf32) fused MLP.
// tcgen05 is unavailable (harness emits non-'a' compute_103 PTX), so layers
// run on the classic HMMA tensor-core path: mma.sync.m16n8k8.row.col.tf32.
//
// CTA = 128 pairs (one i, one j-tile of 128), 128 threads = 4 warps.
// Warp w owns pairs [32w, 32w+32): computes their SH rows, layer1/2/3 mma,
// and silu epilogues. Only ONE __syncthreads (after weight staging); all
// later hazards are warp-local (each warp reads only what it wrote).
//
//   A1[128x16] = [sh(9) | 1 | 0..]  (ones column folds b1)
//   L1: D1 = A1 @ W1s   (W1s[k][n], k=9 row = b1)   -> silu -> AS (tf32)
//   L2: D2 = AS @ W2s + b2                           -> silu -> AS (tf32)
//   L3: D3 = AS @ W3s (+ b3 at store)                -> OS -> coalesced STG

#define S_DIM 1024
#define EPSF 1e-6f

// float-unit offsets into dynamic smem
#define F_AS   0        // [128][68]  activations (stride 68: conflict-free frags)
#define F_W2S  8704     // [64][68]
#define F_SHS  13056    // [128][20]  A1 (stride 20: conflict-free frags)
#define F_W1S  15616    // [16][68]
#define F_W3S  16704    // [64][8]    (stride 8: conflict-free b-frags)
#define F_OS   17216    // [128][9]   layer-3 staging for coalesced stores
#define F_B2S  18368    // [64]
#define F_B3S  18432    // [8]
#define SMEM_FLOATS 18440
#define SMEM_BYTES  (SMEM_FLOATS * 4)

static __device__ __forceinline__ float to_tf32(float x) {
    uint32_t r;
    asm("cvt.rna.tf32.f32 %0, %1;" : "=r"(r) : "f"(x));
    return __uint_as_float(r);
}
static __device__ __forceinline__ float silu_f(float x) {
    return __fdividef(x, 1.0f + __expf(-x));
}
// D += A(16x8,row) * B(8x8,col), tf32 inputs (bit patterns in .b32 regs)
static __device__ __forceinline__ void mma_tf32(float* d, const float* a, const float* b) {
    asm("mma.sync.aligned.m16n8k8.row.col.f32.tf32.tf32.f32 "
        "{%0,%1,%2,%3}, {%4,%5,%6,%7}, {%8,%9}, {%0,%1,%2,%3};"
        : "+f"(d[0]), "+f"(d[1]), "+f"(d[2]), "+f"(d[3])
        : "r"(__float_as_uint(a[0])), "r"(__float_as_uint(a[1])),
          "r"(__float_as_uint(a[2])), "r"(__float_as_uint(a[3])),
          "r"(__float_as_uint(b[0])), "r"(__float_as_uint(b[1])));
}

__global__ void __launch_bounds__(128, 3)
shab_kernel(const float* __restrict__ coords,
            const float* __restrict__ w1, const float* __restrict__ b1,
            const float* __restrict__ w2, const float* __restrict__ b2,
            const float* __restrict__ w3, const float* __restrict__ b3,
            float* __restrict__ out)
{
    extern __shared__ float smf[];
    const int tid  = threadIdx.x;
    const int wid  = tid >> 5;
    const int lane = tid & 31;
    const int gid  = lane >> 2;   // group-of-4 id (0..7)
    const int tig  = lane & 3;    // thread-in-group (0..3)

    // ---- stage weights (tf32) + biases ----
    for (int idx = tid; idx < 16 * 64; idx += 128) {          // W1s[k][n] (+b1 at k=9)
        const int k = idx >> 6, n = idx & 63;
        float v = (k < 9) ? w1[k * 64 + n] : ((k == 9) ? b1[n] : 0.0f);
        smf[F_W1S + k * 68 + n] = to_tf32(v);
    }
    for (int idx = tid; idx < 64 * 64; idx += 128) {          // W2s[k][n]
        const int k = idx >> 6, n = idx & 63;
        smf[F_W2S + k * 68 + n] = to_tf32(w2[idx]);
    }
    for (int idx = tid; idx < 64 * 8; idx += 128) {           // W3s[k][h]
        const int k = idx >> 3, h = idx & 7;
        smf[F_W3S + k * 8 + h] = to_tf32(w3[idx]);
    }
    if (tid < 64) smf[F_B2S + tid] = b2[tid];
    if (tid < 8)  smf[F_B3S + tid] = b3[tid];

    // ---- SH for pair p = tid -> A1 row (tf32), cols [sh0..sh8, 1, 0..0] ----
    const int i  = blockIdx.y;
    const int bb = blockIdx.z;
    const int j  = blockIdx.x * 128 + tid;
    {
        const float* cb = coords + (size_t)bb * (S_DIM * 3);
        const float rx = cb[i * 3 + 0] - cb[j * 3 + 0];
        const float ry = cb[i * 3 + 1] - cb[j * 3 + 1];
        const float rz = cb[i * 3 + 2] - cb[j * 3 + 2];
        const float nrm = sqrtf(rx * rx + ry * ry + rz * rz);
        const float inv = __fdividef(1.0f, nrm + EPSF);
        float ux = rx * inv, uy = ry * inv, uz = rz * inv;
        const float un = sqrtf(ux * ux + uy * uy + uz * uz);
        const float sc = __fdividef(1.0f, fmaxf(un, EPSF));
        ux *= sc; uy *= sc; uz *= sc;

        const float C0    = 0.28209479177387814f;
        const float C1    = 0.48860251190291992f;
        const float C2    = 0.63078313050504009f;
        const float C2S3  = 1.09254843059207907f;
        const float C2S3H = 0.54627421529603953f;

        float* row = smf + F_SHS + tid * 20;
        row[0] = to_tf32(C0);
        row[1] = to_tf32(C1 * ux);
        row[2] = to_tf32(C1 * uy);
        row[3] = to_tf32(C1 * uz);
        row[4] = to_tf32(C2S3 * ux * uz);
        row[5] = to_tf32(C2S3 * ux * uy);
        row[6] = to_tf32(C2 * (uy * uy - 0.5f * (ux * ux + uz * uz)));
        row[7] = to_tf32(C2S3 * uy * uz);
        row[8] = to_tf32(C2S3H * (uz * uz - ux * ux));
        row[9] = 1.0f;                       // b1 fold
        row[10] = row[11] = row[12] = row[13] = row[14] = row[15] = 0.0f;
    }
    __syncthreads();   // the only full barrier

    const int r0 = wid * 32;      // this warp's first pair

    // ---- layer 1: D1[2mt][8nt] = A1 @ W1s  (K=16 -> 2 k-tiles) ----
    float d1[2][8][4];
#pragma unroll
    for (int mt = 0; mt < 2; mt++)
#pragma unroll
        for (int nt = 0; nt < 8; nt++)
#pragma unroll
            for (int q = 0; q < 4; q++) d1[mt][nt][q] = 0.0f;

#pragma unroll
    for (int kt = 0; kt < 2; kt++) {
        float a[2][4];
#pragma unroll
        for (int mt = 0; mt < 2; mt++) {
            const int rr = r0 + mt * 16;
            a[mt][0] = smf[F_SHS + (rr + gid)     * 20 + kt * 8 + tig];
            a[mt][1] = smf[F_SHS + (rr + gid + 8) * 20 + kt * 8 + tig];
            a[mt][2] = smf[F_SHS + (rr + gid)     * 20 + kt * 8 + tig + 4];
            a[mt][3] = smf[F_SHS + (rr + gid + 8) * 20 + kt * 8 + tig + 4];
        }
#pragma unroll
        for (int nt = 0; nt < 8; nt++) {
            float bfr[2];
            bfr[0] = smf[F_W1S + (kt * 8 + tig)     * 68 + nt * 8 + gid];
            bfr[1] = smf[F_W1S + (kt * 8 + tig + 4) * 68 + nt * 8 + gid];
            mma_tf32(d1[0][nt], a[0], bfr);
            mma_tf32(d1[1][nt], a[1], bfr);
        }
    }

    // ---- epi1: silu(D1) -> AS (tf32) ----
#pragma unroll
    for (int mt = 0; mt < 2; mt++) {
        const int pr = r0 + mt * 16 + gid;
#pragma unroll
        for (int nt = 0; nt < 8; nt++) {
            const int ch = nt * 8 + 2 * tig;
            float2 v0, v1;
            v0.x = to_tf32(silu_f(d1[mt][nt][0]));
            v0.y = to_tf32(silu_f(d1[mt][nt][1]));
            v1.x = to_tf32(silu_f(d1[mt][nt][2]));
            v1.y = to_tf32(silu_f(d1[mt][nt][3]));
            *(float2*)(smf + F_AS + pr       * 68 + ch) = v0;
            *(float2*)(smf + F_AS + (pr + 8) * 68 + ch) = v1;
        }
    }
    __syncwarp();   // warp-local: this warp reads only its own AS rows

    // ---- layer 2: D2 = AS @ W2s  (K=64 -> 8 k-tiles) ----
    float d2[2][8][4];
#pragma unroll
    for (int mt = 0; mt < 2; mt++)
#pragma unroll
        for (int nt = 0; nt < 8; nt++)
#pragma unroll
            for (int q = 0; q < 4; q++) d2[mt][nt][q] = 0.0f;

#pragma unroll
    for (int kt = 0; kt < 8; kt++) {
        float a[2][4];
#pragma unroll
        for (int mt = 0; mt < 2; mt++) {
            const int rr = r0 + mt * 16;
            a[mt][0] = smf[F_AS + (rr + gid)     * 68 + kt * 8 + tig];
            a[mt][1] = smf[F_AS + (rr + gid + 8) * 68 + kt * 8 + tig];
            a[mt][2] = smf[F_AS + (rr + gid)     * 68 + kt * 8 + tig + 4];
            a[mt][3] = smf[F_AS + (rr + gid + 8) * 68 + kt * 8 + tig + 4];
        }
#pragma unroll
        for (int nt = 0; nt < 8; nt++) {
            float bfr[2];
            bfr[0] = smf[F_W2S + (kt * 8 + tig)     * 68 + nt * 8 + gid];
            bfr[1] = smf[F_W2S + (kt * 8 + tig + 4) * 68 + nt * 8 + gid];
            mma_tf32(d2[0][nt], a[0], bfr);
            mma_tf32(d2[1][nt], a[1], bfr);
        }
    }
    __syncwarp();   // all AS reads done before overwrite

    // ---- epi2: silu(D2 + b2) -> AS (tf32) ----
#pragma unroll
    for (int mt = 0; mt < 2; mt++) {
        const int pr = r0 + mt * 16 + gid;
#pragma unroll
        for (int nt = 0; nt < 8; nt++) {
            const int ch = nt * 8 + 2 * tig;
            const float bz0 = smf[F_B2S + ch];
            const float bz1 = smf[F_B2S + ch + 1];
            float2 v0, v1;
            v0.x = to_tf32(silu_f(d2[mt][nt][0] + bz0));
            v0.y = to_tf32(silu_f(d2[mt][nt][1] + bz1));
            v1.x = to_tf32(silu_f(d2[mt][nt][2] + bz0));
            v1.y = to_tf32(silu_f(d2[mt][nt][3] + bz1));
            *(float2*)(smf + F_AS + pr       * 68 + ch) = v0;
            *(float2*)(smf + F_AS + (pr + 8) * 68 + ch) = v1;
        }
    }
    __syncwarp();

    // ---- layer 3: D3 = AS @ W3s  (N=8, K=64) ----
    float d3[2][4];
#pragma unroll
    for (int mt = 0; mt < 2; mt++)
#pragma unroll
        for (int q = 0; q < 4; q++) d3[mt][q] = 0.0f;

#pragma unroll
    for (int kt = 0; kt < 8; kt++) {
        float a[2][4];
#pragma unroll
        for (int mt = 0; mt < 2; mt++) {
            const int rr = r0 + mt * 16;
            a[mt][0] = smf[F_AS + (rr + gid)     * 68 + kt * 8 + tig];
            a[mt][1] = smf[F_AS + (rr + gid + 8) * 68 + kt * 8 + tig];
            a[mt][2] = smf[F_AS + (rr + gid)     * 68 + kt * 8 + tig + 4];
            a[mt][3] = smf[F_AS + (rr + gid + 8) * 68 + kt * 8 + tig + 4];
        }
        float bfr[2];
        bfr[0] = smf[F_W3S + (kt * 8 + tig)     * 8 + gid];
        bfr[1] = smf[F_W3S + (kt * 8 + tig + 4) * 8 + gid];
        mma_tf32(d3[0], a[0], bfr);
        mma_tf32(d3[1], a[1], bfr);
    }

    // ---- epi3: D3 -> OS, then coalesced (+b3) stores ----
#pragma unroll
    for (int mt = 0; mt < 2; mt++) {
        const int pr = mt * 16 + gid;   // row within warp's 32 pairs
        smf[F_OS + (r0 + pr)     * 9 + 2 * tig]     = d3[mt][0];
        smf[F_OS + (r0 + pr)     * 9 + 2 * tig + 1] = d3[mt][1];
        smf[F_OS + (r0 + pr + 8) * 9 + 2 * tig]     = d3[mt][2];
        smf[F_OS + (r0 + pr + 8) * 9 + 2 * tig + 1] = d3[mt][3];
    }
    __syncwarp();   // thread tid reads OS row tid, written by its own warp

    {
        const size_t jb = (size_t)blockIdx.x * 128 + tid;
#pragma unroll
        for (int h = 0; h < 8; h++) {
            const size_t o = (((size_t)bb * 8 + h) * S_DIM + i) * S_DIM + jb;
            out[o] = smf[F_OS + tid * 9 + h] + smf[F_B3S + h];
        }
    }
}

extern "C" void kernel_launch(void* const* d_in, const int* in_sizes, int n_in,
                              void* d_out, int out_size) {
    const float* coords = (const float*)d_in[0];
    const float* w1     = (const float*)d_in[1];
    const float* b1     = (const float*)d_in[2];
    const float* w2     = (const float*)d_in[3];
    const float* b2     = (const float*)d_in[4];
    const float* w3     = (const float*)d_in[5];
    const float* b3     = (const float*)d_in[6];
    float* out = (float*)d_out;

    cudaFuncSetAttribute(shab_kernel, cudaFuncAttributeMaxDynamicSharedMemorySize, SMEM_BYTES);
    dim3 grid(S_DIM / 128, S_DIM, 2);  // (j-tiles, i, b)
    shab_kernel<<<grid, 128, SMEM_BYTES>>>(coords, w1, b1, w2, b2, w3, b3, out);
}